// round 12
// baseline (speedup 1.0000x reference)
#include <cuda_runtime.h>
#include <cuda_bf16.h>

// ---------------------------------------------------------------------------
// 18-qubit statevector fidelity |<psi2|psi1>|^2, hardware-efficient ansatz.
// R12 = R11 staircase fusion (7 pass kernels) +
//  (1) per-block inline gate-matrix computation (prep kernel eliminated)
//  (2) reduce+final fused via fence+counter last-block pattern
//  (3) fused kernels use 2 smem transposes instead of 3: round-2 applies its
//      m2 gates first (same-layer gates commute), transposes back to m1,
//      applies m1 gates, stores in m1 layout (coalesced).
// Schedule: P1 A:G0(0-9),init | P2 B:G0hi,CZ0,G1hi | P3 A:G1lo,CZ1,G2lo |
//           P4 B:G2hi,CZ2,G3hi | P5 A:G3lo,CZ3,G4lo | P6 B:G4hi,CZ4,G5hi |
//           P7 A:G5lo,CZ5 | reduce(+final)
// ---------------------------------------------------------------------------

#define NQ 18
#define NL 6
#define NSTATE (1 << NQ)

__device__ float2 d_psi[2][NSTATE];
__device__ double d_acc[2];
__device__ unsigned d_count;

__device__ __forceinline__ float2 cmulh(float2 a, float2 b) {
    return make_float2(a.x * b.x - a.y * b.y, a.x * b.y + a.y * b.x);
}
__device__ __forceinline__ float2 caddh(float2 a, float2 b) {
    return make_float2(a.x + b.x, a.y + b.y);
}
__device__ __forceinline__ float2 rscaleh(float r, float2 v) {
    return make_float2(r * v.x, r * v.y);
}

// fused M = RZ(c)*RY(b)*RX(a) for (state s, layer l, qubit q)
__device__ __forceinline__ void compute_mat(int s, int l, int q,
                                            const float* __restrict__ x1,
                                            const float* __restrict__ x2,
                                            const float* __restrict__ iscale,
                                            const float* __restrict__ var,
                                            float4& o0, float4& o1) {
    const float* x = s ? x2 : x1;
    float a = iscale[l * NQ + q] * x[q];
    float b = var[l * 2 * NQ + q];
    float c = var[l * 2 * NQ + NQ + q];

    float sa, ca, sb, cb, sc, cc;
    sincosf(0.5f * a, &sa, &ca);
    sincosf(0.5f * b, &sb, &cb);
    sincosf(0.5f * c, &sc, &cc);

    float2 X00 = make_float2(ca, 0.f), X01 = make_float2(0.f, -sa);
    float2 X10 = make_float2(0.f, -sa), X11 = make_float2(ca, 0.f);
    float2 M100 = caddh(rscaleh(cb, X00), rscaleh(-sb, X10));
    float2 M101 = caddh(rscaleh(cb, X01), rscaleh(-sb, X11));
    float2 M110 = caddh(rscaleh(sb, X00), rscaleh(cb, X10));
    float2 M111 = caddh(rscaleh(sb, X01), rscaleh(cb, X11));
    float2 e0 = make_float2(cc, -sc);
    float2 e1 = make_float2(cc, sc);
    float2 m00 = cmulh(e0, M100);
    float2 m01 = cmulh(e0, M101);
    float2 m10 = cmulh(e1, M110);
    float2 m11 = cmulh(e1, M111);
    o0 = make_float4(m00.x, m00.y, m01.x, m01.y);
    o1 = make_float4(m10.x, m10.y, m11.x, m11.y);
}

__device__ __forceinline__ void gate_pair(float2& a, float2& b, float4 c0, float4 c1) {
    float nax = fmaf(c0.z, b.x, fmaf(-c0.w, b.y, fmaf(c0.x, a.x, -c0.y * a.y)));
    float nay = fmaf(c0.z, b.y, fmaf(c0.w, b.x, fmaf(c0.x, a.y, c0.y * a.x)));
    float nbx = fmaf(c1.z, b.x, fmaf(-c1.w, b.y, fmaf(c1.x, a.x, -c1.y * a.y)));
    float nby = fmaf(c1.z, b.y, fmaf(c1.w, b.x, fmaf(c1.x, a.y, c1.y * a.x)));
    a = make_float2(nax, nay);
    b = make_float2(nbx, nby);
}

__device__ __forceinline__ float2 gate_shfl(float2 v, int mask,
                                            float cax, float cay, float cbx, float cby) {
    float px = __shfl_xor_sync(0xFFFFFFFFu, v.x, mask);
    float py = __shfl_xor_sync(0xFFFFFFFFu, v.y, mask);
    float rx = fmaf(cbx, px, fmaf(-cby, py, fmaf(cax, v.x, -cay * v.y)));
    float ry = fmaf(cbx, py, fmaf(cby, px, fmaf(cax, v.y, cay * v.x)));
    return make_float2(rx, ry);
}

// smem swizzle (R7/R11, conflict-free for both transpose directions)
__device__ __forceinline__ unsigned swz(unsigned l) {
    return l ^ ((l >> 4) & 3u);
}

#define SHFL_GATE_M(M, j, mask)                                               \
    {                                                                         \
        float4 c0 = (M)[2 * (j)], c1 = (M)[2 * (j) + 1];                      \
        bool hi = (lane & (mask)) != 0;                                       \
        float cax = hi ? c1.z : c0.x;                                         \
        float cay = hi ? c1.w : c0.y;                                         \
        float cbx = hi ? c1.x : c0.z;                                         \
        float cby = hi ? c1.y : c0.w;                                         \
        _Pragma("unroll") for (int k = 0; k < 4; k++)                         \
            v[k] = gate_shfl(v[k], (mask), cax, cay, cbx, cby);               \
    }

// ---------------------------------------------------------------------------
// Window-A kernel: gates q0-9 of layer l1 (and l2 if >=0), CZ after l1 round.
// m1: l = k | lane<<2 | w<<7 ; m2: l = (lane&15) | ((lane>>4)<<9) | w<<4 | k<<7
// Fused path: m1(l1), T1, m2(l1), CZ, m2(l2), T-back, m1(l2), store m1.
// ---------------------------------------------------------------------------
__global__ void __launch_bounds__(256) qk_A(int l1, int l2, int czf, int init,
                                            const float* __restrict__ x1,
                                            const float* __restrict__ x2,
                                            const float* __restrict__ iscale,
                                            const float* __restrict__ var) {
    __shared__ float2 sm[1024];
    __shared__ float4 sM[40];
    int tid = threadIdx.x;
    int lane = tid & 31;
    unsigned w = (unsigned)(tid >> 5);
    int blk = blockIdx.x;
    int s = blk >> 8;
    unsigned blkbase = ((unsigned)(blk & 255)) << 10;
    float2* psi = d_psi[s];

    if (init && blk == 0 && tid == 0) {
        d_acc[0] = 0.0;
        d_acc[1] = 0.0;
        d_count = 0u;
    }

    if (tid < 10) {
        float4 a0, a1;
        compute_mat(s, l1, tid, x1, x2, iscale, var, a0, a1);
        sM[2 * tid] = a0;
        sM[2 * tid + 1] = a1;
    }
    if (l2 >= 0 && tid >= 32 && tid < 42) {
        int q = tid - 32;
        float4 a0, a1;
        compute_mat(s, l2, q, x1, x2, iscale, var, a0, a1);
        sM[20 + 2 * q] = a0;
        sM[21 + 2 * q] = a1;
    }

    unsigned l1i = ((unsigned)lane << 2) | (w << 7);
    unsigned base2 = ((unsigned)lane & 15u) | (((unsigned)lane >> 4) << 9) | (w << 4);
    float2 v[4];

    if (init) {
#pragma unroll
        for (int k = 0; k < 4; k++) v[k] = make_float2(0.f, 0.f);
        if ((blkbase | l1i) == 0) v[0] = make_float2(1.f, 0.f);
    } else {
        const float4* p4 = (const float4*)(psi + blkbase + l1i);
        float4 a = p4[0], b = p4[1];
        v[0] = make_float2(a.x, a.y);
        v[1] = make_float2(a.z, a.w);
        v[2] = make_float2(b.x, b.y);
        v[3] = make_float2(b.z, b.w);
    }
    __syncthreads();                                // sM ready

    // ---- round 1, m1 gates: q0 (k s1), q1 (k s2), q2-6 (lane shfl)
    {
        float4 c0 = sM[0], c1 = sM[1];
        gate_pair(v[0], v[1], c0, c1);
        gate_pair(v[2], v[3], c0, c1);
    }
    {
        float4 c0 = sM[2], c1 = sM[3];
        gate_pair(v[0], v[2], c0, c1);
        gate_pair(v[1], v[3], c0, c1);
    }
    SHFL_GATE_M(sM, 2, 1)
    SHFL_GATE_M(sM, 3, 2)
    SHFL_GATE_M(sM, 4, 4)
    SHFL_GATE_M(sM, 5, 8)
    SHFL_GATE_M(sM, 6, 16)

    // T1: m1 -> m2
    unsigned sb1 = swz(l1i);
#pragma unroll
    for (int k = 0; k < 4; k++) sm[sb1 ^ (unsigned)k] = v[k];
    __syncthreads();
    unsigned sb2 = swz(base2);
#pragma unroll
    for (int k = 0; k < 4; k++) v[k] = sm[sb2 + ((unsigned)k << 7)];

    // ---- round 1, m2 gates: q7 (k' s1), q8 (k' s2), q9 (lane bit4 shfl)
    {
        float4 c0 = sM[14], c1 = sM[15];
        gate_pair(v[0], v[1], c0, c1);
        gate_pair(v[2], v[3], c0, c1);
    }
    {
        float4 c0 = sM[16], c1 = sM[17];
        gate_pair(v[0], v[2], c0, c1);
        gate_pair(v[1], v[3], c0, c1);
    }
    SHFL_GATE_M(sM, 9, 16)

    // CZ chain sign (after layer l1 complete)
    if (czf >= 0) {
#pragma unroll
        for (int k = 0; k < 4; k++) {
            unsigned g = blkbase + base2 + ((unsigned)k << 7);
            unsigned tm = g & (g >> 1) & 0x1FFFFu;
            if (__popc(tm) & 1) {
                v[k].x = -v[k].x;
                v[k].y = -v[k].y;
            }
        }
    }

    if (l2 < 0) {
        // store m2 (coalesced 128B runs)
#pragma unroll
        for (int k = 0; k < 4; k++)
            psi[blkbase + base2 + ((unsigned)k << 7)] = v[k];
        return;
    }

    const float4* M2 = sM + 20;
    // ---- round 2, m2 gates FIRST (same-layer gates commute): q7, q8, q9
    {
        float4 c0 = M2[14], c1 = M2[15];
        gate_pair(v[0], v[1], c0, c1);
        gate_pair(v[2], v[3], c0, c1);
    }
    {
        float4 c0 = M2[16], c1 = M2[17];
        gate_pair(v[0], v[2], c0, c1);
        gate_pair(v[1], v[3], c0, c1);
    }
    SHFL_GATE_M(M2, 9, 16)

    // T-back: m2 -> m1
    __syncthreads();                                // all T1 reads done
#pragma unroll
    for (int k = 0; k < 4; k++) sm[sb2 + ((unsigned)k << 7)] = v[k];
    __syncthreads();
#pragma unroll
    for (int k = 0; k < 4; k++) v[k] = sm[sb1 ^ (unsigned)k];

    // ---- round 2, m1 gates: q0, q1, q2-6
    {
        float4 c0 = M2[0], c1 = M2[1];
        gate_pair(v[0], v[1], c0, c1);
        gate_pair(v[2], v[3], c0, c1);
    }
    {
        float4 c0 = M2[2], c1 = M2[3];
        gate_pair(v[0], v[2], c0, c1);
        gate_pair(v[1], v[3], c0, c1);
    }
    SHFL_GATE_M(M2, 2, 1)
    SHFL_GATE_M(M2, 3, 2)
    SHFL_GATE_M(M2, 4, 4)
    SHFL_GATE_M(M2, 5, 8)
    SHFL_GATE_M(M2, 6, 16)

    // store m1 (fully coalesced float4s)
    {
        float4* p4 = (float4*)(psi + blkbase + l1i);
        p4[0] = make_float4(v[0].x, v[0].y, v[1].x, v[1].y);
        p4[1] = make_float4(v[2].x, v[2].y, v[3].x, v[3].y);
    }
}

// ---------------------------------------------------------------------------
// Window-B kernel: gates q10-17 of layer l1 (and l2 if >=0), CZ after l1.
// Window {0,1,10..17}: g(l) = (l&3) | rest<<2 | (l>>2)<<10.
// Fused path: m1(l1), T1, m2(l1), CZ, m2(l2), T-back, m1(l2), store m1 (=g1).
// ---------------------------------------------------------------------------
__global__ void __launch_bounds__(256) qk_B(int l1, int l2, int czf,
                                            const float* __restrict__ x1,
                                            const float* __restrict__ x2,
                                            const float* __restrict__ iscale,
                                            const float* __restrict__ var) {
    __shared__ float2 sm[1024];
    __shared__ float4 sM[32];
    int tid = threadIdx.x;
    int lane = tid & 31;
    unsigned w = (unsigned)(tid >> 5);
    int blk = blockIdx.x;
    int s = blk >> 8;
    unsigned rest = (unsigned)(blk & 255);
    float2* psi = d_psi[s];

    if (tid < 8) {
        float4 a0, a1;
        compute_mat(s, l1, 10 + tid, x1, x2, iscale, var, a0, a1);
        sM[2 * tid] = a0;
        sM[2 * tid + 1] = a1;
    }
    if (l2 >= 0 && tid >= 32 && tid < 40) {
        int j = tid - 32;
        float4 a0, a1;
        compute_mat(s, l2, 10 + j, x1, x2, iscale, var, a0, a1);
        sM[16 + 2 * j] = a0;
        sM[17 + 2 * j] = a1;
    }

    unsigned l1i = ((unsigned)lane << 2) | (w << 7);
    unsigned g1 = (l1i & 3u) | (rest << 2) | ((l1i >> 2) << 10);
    unsigned base2 = ((unsigned)lane & 15u) | (((unsigned)lane >> 4) << 9) | (w << 4);

    float2 v[4];
    {
        const float4* p4 = (const float4*)(psi + g1);
        float4 a = p4[0], b = p4[1];
        v[0] = make_float2(a.x, a.y);
        v[1] = make_float2(a.z, a.w);
        v[2] = make_float2(b.x, b.y);
        v[3] = make_float2(b.z, b.w);
    }
    __syncthreads();                                // sM ready

    // ---- round 1, m1 gates: q10..q14 (lane shfl; j = q-10)
    SHFL_GATE_M(sM, 0, 1)
    SHFL_GATE_M(sM, 1, 2)
    SHFL_GATE_M(sM, 2, 4)
    SHFL_GATE_M(sM, 3, 8)
    SHFL_GATE_M(sM, 4, 16)

    // T1
    unsigned sb1 = swz(l1i);
#pragma unroll
    for (int k = 0; k < 4; k++) sm[sb1 ^ (unsigned)k] = v[k];
    __syncthreads();
    unsigned sb2 = swz(base2);
#pragma unroll
    for (int k = 0; k < 4; k++) v[k] = sm[sb2 + ((unsigned)k << 7)];

    // ---- round 1, m2 gates: q15 (k' s1), q16 (k' s2), q17 (lane bit4 shfl)
    {
        float4 c0 = sM[10], c1 = sM[11];
        gate_pair(v[0], v[1], c0, c1);
        gate_pair(v[2], v[3], c0, c1);
    }
    {
        float4 c0 = sM[12], c1 = sM[13];
        gate_pair(v[0], v[2], c0, c1);
        gate_pair(v[1], v[3], c0, c1);
    }
    SHFL_GATE_M(sM, 7, 16)

    // CZ chain sign
    if (czf >= 0) {
#pragma unroll
        for (int k = 0; k < 4; k++) {
            unsigned l2i = base2 | ((unsigned)k << 7);
            unsigned g = (l2i & 3u) | (rest << 2) | ((l2i >> 2) << 10);
            unsigned tm = g & (g >> 1) & 0x1FFFFu;
            if (__popc(tm) & 1) {
                v[k].x = -v[k].x;
                v[k].y = -v[k].y;
            }
        }
    }

    if (l2 < 0) {
#pragma unroll
        for (int k = 0; k < 4; k++) {
            unsigned l2i = base2 | ((unsigned)k << 7);
            unsigned g = (l2i & 3u) | (rest << 2) | ((l2i >> 2) << 10);
            psi[g] = v[k];
        }
        return;
    }

    const float4* M2 = sM + 16;
    // ---- round 2, m2 gates first: q15, q16, q17
    {
        float4 c0 = M2[10], c1 = M2[11];
        gate_pair(v[0], v[1], c0, c1);
        gate_pair(v[2], v[3], c0, c1);
    }
    {
        float4 c0 = M2[12], c1 = M2[13];
        gate_pair(v[0], v[2], c0, c1);
        gate_pair(v[1], v[3], c0, c1);
    }
    SHFL_GATE_M(M2, 7, 16)

    // T-back
    __syncthreads();
#pragma unroll
    for (int k = 0; k < 4; k++) sm[sb2 + ((unsigned)k << 7)] = v[k];
    __syncthreads();
#pragma unroll
    for (int k = 0; k < 4; k++) v[k] = sm[sb1 ^ (unsigned)k];

    // ---- round 2, m1 gates: q10..q14
    SHFL_GATE_M(M2, 0, 1)
    SHFL_GATE_M(M2, 1, 2)
    SHFL_GATE_M(M2, 2, 4)
    SHFL_GATE_M(M2, 3, 8)
    SHFL_GATE_M(M2, 4, 16)

    // store m1 (same pattern as load)
    {
        float4* p4 = (float4*)(psi + g1);
        p4[0] = make_float4(v[0].x, v[0].y, v[1].x, v[1].y);
        p4[1] = make_float4(v[2].x, v[2].y, v[3].x, v[3].y);
    }
}

// ---------------------------------------------------------------------------
// Overlap reduction + finalization (last block computes |ov|^2)
// ---------------------------------------------------------------------------
__global__ void qk_reduce(float* out) {
    int t = blockIdx.x * blockDim.x + threadIdx.x;
    int nthreads = gridDim.x * blockDim.x;
    double re = 0.0, im = 0.0;
    for (int i = t; i < NSTATE; i += nthreads) {
        float2 a = d_psi[0][i];
        float2 b = d_psi[1][i];
        re += (double)b.x * a.x + (double)b.y * a.y;
        im += (double)b.x * a.y - (double)b.y * a.x;
    }
#pragma unroll
    for (int o = 16; o > 0; o >>= 1) {
        re += __shfl_down_sync(0xFFFFFFFFu, re, o);
        im += __shfl_down_sync(0xFFFFFFFFu, im, o);
    }
    if ((threadIdx.x & 31) == 0) {
        atomicAdd(&d_acc[0], re);
        atomicAdd(&d_acc[1], im);
    }
    __syncthreads();
    if (threadIdx.x == 0) {
        __threadfence();
        unsigned done = atomicAdd(&d_count, 1u);
        if (done == gridDim.x - 1) {
            double rr = d_acc[0], ii = d_acc[1];
            out[0] = (float)(rr * rr + ii * ii);
        }
    }
}

extern "C" void kernel_launch(void* const* d_in, const int* in_sizes, int n_in,
                              void* d_out, int out_size) {
    const float* x1 = (const float*)d_in[0];
    const float* x2 = (const float*)d_in[1];
    const float* iscale = (const float*)d_in[2];
    const float* var = (const float*)d_in[3];

    qk_A<<<512, 256>>>(0, -1, -1, 1, x1, x2, iscale, var);   // G0(0-9), init
    qk_B<<<512, 256>>>(0, 1, 0, x1, x2, iscale, var);        // G0hi, CZ0, G1hi
    qk_A<<<512, 256>>>(1, 2, 1, 0, x1, x2, iscale, var);     // G1lo, CZ1, G2lo
    qk_B<<<512, 256>>>(2, 3, 2, x1, x2, iscale, var);        // G2hi, CZ2, G3hi
    qk_A<<<512, 256>>>(3, 4, 3, 0, x1, x2, iscale, var);     // G3lo, CZ3, G4lo
    qk_B<<<512, 256>>>(4, 5, 4, x1, x2, iscale, var);        // G4hi, CZ4, G5hi
    qk_A<<<512, 256>>>(5, -1, 5, 0, x1, x2, iscale, var);    // G5lo, CZ5
    qk_reduce<<<148, 256>>>((float*)d_out);
}